// round 3
// baseline (speedup 1.0000x reference)
#include <cuda_runtime.h>
#include <math.h>

#define NN_MAX 50000
#define NE_MAX 800000

// ---------------- device scratch (static, allocation-free) ----------------
__device__ float g_Z[(size_t)NN_MAX * 128];   // transformed features (h @ W)
__device__ float g_H[(size_t)NN_MAX * 128];   // aggregated activations
__device__ float g_dinv[NN_MAX];
__device__ int   g_count[NN_MAX];
__device__ int   g_cursor[NN_MAX];
__device__ int   g_off[NN_MAX + 1];
__device__ int   g_src[NE_MAX];
__device__ int   g_is64;                      // 1 if edge_index/y are int64

// ---------------- int32/int64 index helper ----------------
__device__ __forceinline__ int edge_val(const void* ei, int E, int which, int e) {
    if (g_is64) return (int)((const long long*)ei)[(size_t)which * E + e];
    return ((const int*)ei)[(size_t)which * E + e];
}

// Detect whether edge_index is int64: if so, every odd 32-bit word (high word
// of a small nonnegative value) is zero. For int32 data these words are node
// indices, essentially never all zero across 1024 samples.
__global__ void detect_k(const int* __restrict__ ei) {
    __shared__ int any;
    if (threadIdx.x == 0) any = 0;
    __syncthreads();
    int local = 0;
    for (int i = threadIdx.x; i < 1024; i += blockDim.x)
        if (ei[2 * i + 1] != 0) local = 1;
    if (local) atomicOr(&any, 1);
    __syncthreads();
    if (threadIdx.x == 0) g_is64 = any ? 0 : 1;
}

__global__ void init_k(int n) {
    int i = blockIdx.x * blockDim.x + threadIdx.x;
    if (i < n) { g_count[i] = 0; g_cursor[i] = 0; }
}

__global__ void count_k(const void* __restrict__ ei, int E) {
    int e = blockIdx.x * blockDim.x + threadIdx.x;
    if (e < E) {
        int dst = edge_val(ei, E, 1, e);
        atomicAdd(&g_count[dst], 1);
    }
}

// Single-block exclusive scan over counts -> offsets; also compute dinv.
__global__ void scan_k(int n) {
    __shared__ int part[1024];
    int t = threadIdx.x;
    int chunk = (n + 1023) >> 10;
    int lo = t * chunk;
    int hi = lo + chunk; if (hi > n) hi = n;
    int s = 0;
    for (int i = lo; i < hi; i++) {
        int c = g_count[i];
        s += c;
        g_dinv[i] = rsqrtf((float)(c + 1));   // +1 for self loop
    }
    part[t] = s;
    __syncthreads();
    for (int off = 1; off < 1024; off <<= 1) {
        int v = (t >= off) ? part[t - off] : 0;
        __syncthreads();
        part[t] += v;
        __syncthreads();
    }
    int pref = (t > 0) ? part[t - 1] : 0;
    for (int i = lo; i < hi; i++) { g_off[i] = pref; pref += g_count[i]; }
    if (t == 1023) g_off[n] = part[1023];
}

__global__ void fill_k(const void* __restrict__ ei, int E) {
    int e = blockIdx.x * blockDim.x + threadIdx.x;
    if (e < E) {
        int dst = edge_val(ei, E, 1, e);
        int src = edge_val(ei, E, 0, e);
        int p = g_off[dst] + atomicAdd(&g_cursor[dst], 1);
        g_src[p] = src;
    }
}

// ---------------- SIMT GEMM: C[M,N] = A[M,K] @ W[K,N] ----------------
// 256 threads = 8 warps, each warp computes 4 rows; lane covers N/32 cols.
template<int K, int N>
__global__ void gemm_k(const float* __restrict__ A, const float* __restrict__ W,
                       float* __restrict__ C, int M) {
    constexpr int CP = N / 32;
    constexpr int KC = (K * N <= 8192) ? K : (8192 / N);   // <=32KB smem
    __shared__ float sW[KC * N];
    int warp = threadIdx.x >> 5, lane = threadIdx.x & 31;
    int r0 = (blockIdx.x * (blockDim.x >> 5) + warp) * 4;
    if (r0 >= M) {
        // still must participate in __syncthreads
    }
    float acc[4][CP];
#pragma unroll
    for (int r = 0; r < 4; r++)
#pragma unroll
        for (int j = 0; j < CP; j++) acc[r][j] = 0.f;

    for (int kc = 0; kc < K; kc += KC) {
        __syncthreads();
        for (int i = threadIdx.x; i < KC * N; i += blockDim.x) sW[i] = W[kc * N + i];
        __syncthreads();
        if (r0 < M) {
            int rr[4];
#pragma unroll
            for (int r = 0; r < 4; r++) { int v = r0 + r; rr[r] = v < M ? v : M - 1; }
#pragma unroll 2
            for (int kk = 0; kk < KC; kk += 4) {
                float4 a[4];
#pragma unroll
                for (int r = 0; r < 4; r++)
                    a[r] = *(const float4*)(A + (size_t)rr[r] * K + kc + kk);
#pragma unroll
                for (int t = 0; t < 4; t++) {
                    float w[CP];
#pragma unroll
                    for (int j = 0; j < CP; j++) w[j] = sW[(kk + t) * N + lane * CP + j];
#pragma unroll
                    for (int r = 0; r < 4; r++) {
                        float av = (t == 0) ? a[r].x : (t == 1) ? a[r].y : (t == 2) ? a[r].z : a[r].w;
#pragma unroll
                        for (int j = 0; j < CP; j++) acc[r][j] = fmaf(av, w[j], acc[r][j]);
                    }
                }
            }
        }
    }
#pragma unroll
    for (int r = 0; r < 4; r++) {
        if (r0 + r < M) {
#pragma unroll
            for (int j = 0; j < CP; j++)
                C[(size_t)(r0 + r) * N + lane * CP + j] = acc[r][j];
        }
    }
}

// ---------------- edge aggregation: H[i] = relu(sum_e w_e * Z[src] + b) ----
// warp per node; self-loop weight dinv^2 folded in; no atomics.
template<int N>
__global__ void agg_k(const float* __restrict__ Z, float* __restrict__ H,
                      const float* __restrict__ b, int n) {
    constexpr int CP = N / 32;
    int node = (blockIdx.x * blockDim.x + threadIdx.x) >> 5;
    int lane = threadIdx.x & 31;
    if (node >= n) return;
    float di = g_dinv[node];
    float acc[CP];
    {
        float w = di * di;  // self loop
        const float* zp = Z + (size_t)node * N + lane * CP;
        if (CP == 4) {
            float4 zv = *(const float4*)zp;
            acc[0] = w * zv.x; acc[1] = w * zv.y;
            acc[2] = w * zv.z; acc[3] = w * zv.w;
        } else {
            float2 zv = *(const float2*)zp;
            acc[0] = w * zv.x; acc[1] = w * zv.y;
        }
    }
    int e = g_off[node], end = g_off[node + 1];
    for (; e < end; e++) {
        int s = g_src[e];
        float w = di * __ldg(&g_dinv[s]);
        const float* zp = Z + (size_t)s * N + lane * CP;
        if (CP == 4) {
            float4 zv = *(const float4*)zp;
            acc[0] = fmaf(w, zv.x, acc[0]); acc[1] = fmaf(w, zv.y, acc[1]);
            acc[2] = fmaf(w, zv.z, acc[2]); acc[3] = fmaf(w, zv.w, acc[3]);
        } else {
            float2 zv = *(const float2*)zp;
            acc[0] = fmaf(w, zv.x, acc[0]); acc[1] = fmaf(w, zv.y, acc[1]);
        }
    }
#pragma unroll
    for (int j = 0; j < CP; j++) {
        float v = acc[j] + __ldg(&b[lane * CP + j]);
        H[(size_t)node * N + lane * CP + j] = v > 0.f ? v : 0.f;
    }
}

// ---------------- prototype distances + MLP readout + sigmoid + y ---------
__global__ void final_k(const float* __restrict__ H, const float* __restrict__ prot,
                        const float* __restrict__ Wf0, const float* __restrict__ bf0,
                        const float* __restrict__ Wf1, const float* __restrict__ bf1,
                        const void* __restrict__ y,
                        float* __restrict__ out, int n, int out_size) {
    __shared__ float sP[16 * 64];
    __shared__ float sPsq[16];
    __shared__ float sW0[16 * 8];
    __shared__ float sb0[8];
    __shared__ float sW1[8];
    __shared__ float sb1;
    for (int i = threadIdx.x; i < 16 * 64; i += blockDim.x) sP[i] = prot[i];
    if (threadIdx.x < 128) {
        if (threadIdx.x < 16 * 8) sW0[threadIdx.x] = Wf0[threadIdx.x];
        if (threadIdx.x < 8) { sb0[threadIdx.x] = bf0[threadIdx.x]; sW1[threadIdx.x] = Wf1[threadIdx.x]; }
        if (threadIdx.x == 0) sb1 = bf1[0];
    }
    __syncthreads();
    if (threadIdx.x < 16) {
        float s = 0.f;
        for (int k = 0; k < 64; k++) { float p = sP[threadIdx.x * 64 + k]; s += p * p; }
        sPsq[threadIdx.x] = s;
    }
    __syncthreads();

    int i = blockIdx.x * blockDim.x + threadIdx.x;
    if (i >= n) return;

    float dot[16];
#pragma unroll
    for (int j = 0; j < 16; j++) dot[j] = 0.f;
    float hh = 0.f;
    const float* h = H + (size_t)i * 64;
    for (int k = 0; k < 64; k++) {
        float hv = h[k];
        hh = fmaf(hv, hv, hh);
#pragma unroll
        for (int j = 0; j < 16; j++) dot[j] = fmaf(hv, sP[j * 64 + k], dot[j]);
    }
    float sim[16];
#pragma unroll
    for (int j = 0; j < 16; j++) {
        float d2 = hh + sPsq[j] - 2.f * dot[j];
        d2 = d2 > 0.f ? d2 : 0.f;
        sim[j] = logf((d2 + 1.0f) / (d2 + 1e-4f));
    }
    float o = sb1;
#pragma unroll
    for (int m = 0; m < 8; m++) {
        float t = sb0[m];
#pragma unroll
        for (int j = 0; j < 16; j++) t = fmaf(sim[j], sW0[j * 8 + m], t);
        float z = 0.5f * t * (1.0f + erff(t * 0.70710678118654752f));  // exact GELU
        o = fmaf(z, sW1[m], o);
    }
    out[i] = 1.0f / (1.0f + expf(-o));

    if (out_size >= 2 * n) {
        float yv;
        if (g_is64) yv = (float)((const long long*)y)[i];
        else        yv = (float)((const int*)y)[i];
        out[n + i] = yv;
    }
}

// ---------------- launch ----------------
extern "C" void kernel_launch(void* const* d_in, const int* in_sizes, int n_in,
                              void* d_out, int out_size) {
    const float* x    = (const float*)d_in[0];
    const void*  ei   = d_in[1];
    const void*  y    = d_in[2];
    const float* W1   = (const float*)d_in[3];
    const float* b1   = (const float*)d_in[4];
    const float* W2   = (const float*)d_in[5];
    const float* b2   = (const float*)d_in[6];
    const float* W3   = (const float*)d_in[7];
    const float* b3   = (const float*)d_in[8];
    const float* prot = (const float*)d_in[9];
    const float* Wf0  = (const float*)d_in[10];
    const float* bf0  = (const float*)d_in[11];
    const float* Wf1  = (const float*)d_in[12];
    const float* bf1  = (const float*)d_in[13];
    float* out = (float*)d_out;

    int n = in_sizes[0] / 128;
    int E = in_sizes[1] / 2;

    void *pZ, *pH;
    cudaGetSymbolAddress(&pZ, g_Z);
    cudaGetSymbolAddress(&pH, g_H);
    float* Z = (float*)pZ;
    float* H = (float*)pH;

    detect_k<<<1, 256>>>((const int*)ei);
    init_k<<<(n + 255) / 256, 256>>>(n);
    count_k<<<(E + 255) / 256, 256>>>(ei, E);
    scan_k<<<1, 1024>>>(n);
    fill_k<<<(E + 255) / 256, 256>>>(ei, E);

    int gemm_grid = (n + 31) / 32;           // 8 warps * 4 rows per block
    int agg_grid  = (n + 7) / 8;             // 8 warps (nodes) per block

    // layer 1: x[n,128] @ W1[128,128] -> Z ; aggregate -> H
    gemm_k<128, 128><<<gemm_grid, 256>>>(x, W1, Z, n);
    agg_k<128><<<agg_grid, 256>>>(Z, H, b1, n);
    // layer 2: H[n,128] @ W2[128,64] -> Z ; aggregate -> H
    gemm_k<128, 64><<<gemm_grid, 256>>>(H, W2, Z, n);
    agg_k<64><<<agg_grid, 256>>>(Z, H, b2, n);
    // layer 3: H[n,64] @ W3[64,64] -> Z ; aggregate -> H
    gemm_k<64, 64><<<gemm_grid, 256>>>(H, W3, Z, n);
    agg_k<64><<<agg_grid, 256>>>(Z, H, b3, n);

    final_k<<<(n + 127) / 128, 128>>>(H, prot, Wf0, bf0, Wf1, bf1, y, out, n, out_size);
}

// round 4
// speedup vs baseline: 1.2298x; 1.2298x over previous
#include <cuda_runtime.h>
#include <math.h>

#define NN_MAX 50000
#define NE_MAX 800000
#define SCAN_B 1024
#define NB_MAX ((NN_MAX + SCAN_B - 1) / SCAN_B)   // 49

// ---------------- device scratch (static, allocation-free) ----------------
__device__ float g_Z[(size_t)NN_MAX * 128];   // transformed features (h @ W)
__device__ float g_H[(size_t)NN_MAX * 128];   // aggregated activations
__device__ float g_dinv[NN_MAX];
__device__ int   g_count[NN_MAX];
__device__ int   g_cursor[NN_MAX];
__device__ int   g_off[NN_MAX + 1];
__device__ int   g_src[NE_MAX];
__device__ float g_w[NE_MAX];                 // per-edge sym-norm weight
__device__ int   g_blk[64];                   // block sums for scan
__device__ int   g_is64;                      // 1 if edge_index/y are int64

// ---------------- int32/int64 index helper ----------------
__device__ __forceinline__ int edge_val(const void* ei, int E, int which, int e) {
    if (g_is64) return (int)((const long long*)ei)[(size_t)which * E + e];
    return ((const int*)ei)[(size_t)which * E + e];
}

// Detect whether edge_index is int64: high 32-bit words of small nonneg
// int64 values are all zero; for int32 data they are node indices.
__global__ void detect_k(const int* __restrict__ ei) {
    __shared__ int any;
    if (threadIdx.x == 0) any = 0;
    __syncthreads();
    int local = 0;
    for (int i = threadIdx.x; i < 1024; i += blockDim.x)
        if (ei[2 * i + 1] != 0) local = 1;
    if (local) atomicOr(&any, 1);
    __syncthreads();
    if (threadIdx.x == 0) g_is64 = any ? 0 : 1;
}

__global__ void init_k(int n) {
    int i = blockIdx.x * blockDim.x + threadIdx.x;
    if (i < n) { g_count[i] = 0; g_cursor[i] = 0; }
}

__global__ void count_k(const void* __restrict__ ei, int E) {
    int e = blockIdx.x * blockDim.x + threadIdx.x;
    if (e < E) {
        int dst = edge_val(ei, E, 1, e);
        atomicAdd(&g_count[dst], 1);
    }
}

// ---- two-pass scan: block-local exclusive scan + dinv ----
__global__ void scan1_k(int n) {
    __shared__ int sh[SCAN_B];
    int i = blockIdx.x * SCAN_B + threadIdx.x;
    int v = (i < n) ? g_count[i] : 0;
    if (i < n) g_dinv[i] = rsqrtf((float)(v + 1));   // +1 self loop
    sh[threadIdx.x] = v;
    __syncthreads();
    for (int off = 1; off < SCAN_B; off <<= 1) {
        int t = (threadIdx.x >= off) ? sh[threadIdx.x - off] : 0;
        __syncthreads();
        sh[threadIdx.x] += t;
        __syncthreads();
    }
    if (i < n) g_off[i] = sh[threadIdx.x] - v;       // exclusive within block
    if (threadIdx.x == SCAN_B - 1) g_blk[blockIdx.x] = sh[SCAN_B - 1];
}

// scan of <=64 block sums (inclusive)
__global__ void scan2_k(int nb) {
    __shared__ int sh[64];
    int t = threadIdx.x;
    sh[t] = (t < nb) ? g_blk[t] : 0;
    __syncthreads();
    for (int off = 1; off < 64; off <<= 1) {
        int v = (t >= off) ? sh[t - off] : 0;
        __syncthreads();
        sh[t] += v;
        __syncthreads();
    }
    g_blk[t] = sh[t];
}

// uniform add of previous-blocks prefix; also set g_off[n]
__global__ void scan3_k(int n, int nb) {
    int i = blockIdx.x * blockDim.x + threadIdx.x;
    if (i < n) {
        int blk = i >> 10;
        if (blk > 0) g_off[i] += g_blk[blk - 1];
    }
    if (i == 0) g_off[n] = g_blk[nb - 1];
}

__global__ void fill_k(const void* __restrict__ ei, int E) {
    int e = blockIdx.x * blockDim.x + threadIdx.x;
    if (e < E) {
        int dst = edge_val(ei, E, 1, e);
        int src = edge_val(ei, E, 0, e);
        int p = g_off[dst] + atomicAdd(&g_cursor[dst], 1);
        g_src[p] = src;
        g_w[p] = g_dinv[src] * g_dinv[dst];
    }
}

// ---------------- SIMT GEMM: C[M,N] = A[M,K] @ W[K,N] ----------------
// 256 threads = 8 warps, each warp computes 4 rows; lane covers N/32 cols.
template<int K, int N>
__global__ void gemm_k(const float* __restrict__ A, const float* __restrict__ W,
                       float* __restrict__ C, int M) {
    constexpr int CP = N / 32;
    constexpr int KC = (K * N <= 8192) ? K : (8192 / N);
    __shared__ float sW[KC * N];
    int warp = threadIdx.x >> 5, lane = threadIdx.x & 31;
    int r0 = (blockIdx.x * (blockDim.x >> 5) + warp) * 4;
    float acc[4][CP];
#pragma unroll
    for (int r = 0; r < 4; r++)
#pragma unroll
        for (int j = 0; j < CP; j++) acc[r][j] = 0.f;

    for (int kc = 0; kc < K; kc += KC) {
        __syncthreads();
        for (int i = threadIdx.x; i < KC * N; i += blockDim.x) sW[i] = W[kc * N + i];
        __syncthreads();
        if (r0 < M) {
            int rr[4];
#pragma unroll
            for (int r = 0; r < 4; r++) { int v = r0 + r; rr[r] = v < M ? v : M - 1; }
#pragma unroll 2
            for (int kk = 0; kk < KC; kk += 4) {
                float4 a[4];
#pragma unroll
                for (int r = 0; r < 4; r++)
                    a[r] = *(const float4*)(A + (size_t)rr[r] * K + kc + kk);
#pragma unroll
                for (int t = 0; t < 4; t++) {
                    float w[CP];
#pragma unroll
                    for (int j = 0; j < CP; j++) w[j] = sW[(kk + t) * N + lane * CP + j];
#pragma unroll
                    for (int r = 0; r < 4; r++) {
                        float av = (t == 0) ? a[r].x : (t == 1) ? a[r].y : (t == 2) ? a[r].z : a[r].w;
#pragma unroll
                        for (int j = 0; j < CP; j++) acc[r][j] = fmaf(av, w[j], acc[r][j]);
                    }
                }
            }
        }
    }
#pragma unroll
    for (int r = 0; r < 4; r++) {
        if (r0 + r < M) {
#pragma unroll
            for (int j = 0; j < CP; j++)
                C[(size_t)(r0 + r) * N + lane * CP + j] = acc[r][j];
        }
    }
}

// ---------------- edge aggregation: H[i] = relu(sum_e w_e * Z[src] + b) ----
// warp per node; 2-edge unroll for MLP; per-edge weights precomputed.
template<int N>
__global__ void agg_k(const float* __restrict__ Z, float* __restrict__ H,
                      const float* __restrict__ b, int n) {
    constexpr int CP = N / 32;
    int node = (blockIdx.x * blockDim.x + threadIdx.x) >> 5;
    int lane = threadIdx.x & 31;
    if (node >= n) return;
    float di = g_dinv[node];
    float acc[CP];
    {
        float w = di * di;  // self loop
        const float* zp = Z + (size_t)node * N + lane * CP;
        if (CP == 4) {
            float4 zv = *(const float4*)zp;
            acc[0] = w * zv.x; acc[1] = w * zv.y;
            acc[2] = w * zv.z; acc[3] = w * zv.w;
        } else {
            float2 zv = *(const float2*)zp;
            acc[0] = w * zv.x; acc[1] = w * zv.y;
        }
    }
    int e = g_off[node], end = g_off[node + 1];
    // 2-edge unrolled main loop (independent loads -> 2x MLP)
    for (; e + 2 <= end; e += 2) {
        int s0 = g_src[e], s1 = g_src[e + 1];
        float w0 = g_w[e], w1 = g_w[e + 1];
        const float* z0 = Z + (size_t)s0 * N + lane * CP;
        const float* z1 = Z + (size_t)s1 * N + lane * CP;
        if (CP == 4) {
            float4 a0 = *(const float4*)z0;
            float4 a1 = *(const float4*)z1;
            acc[0] = fmaf(w0, a0.x, acc[0]); acc[1] = fmaf(w0, a0.y, acc[1]);
            acc[2] = fmaf(w0, a0.z, acc[2]); acc[3] = fmaf(w0, a0.w, acc[3]);
            acc[0] = fmaf(w1, a1.x, acc[0]); acc[1] = fmaf(w1, a1.y, acc[1]);
            acc[2] = fmaf(w1, a1.z, acc[2]); acc[3] = fmaf(w1, a1.w, acc[3]);
        } else {
            float2 a0 = *(const float2*)z0;
            float2 a1 = *(const float2*)z1;
            acc[0] = fmaf(w0, a0.x, acc[0]); acc[1] = fmaf(w0, a0.y, acc[1]);
            acc[0] = fmaf(w1, a1.x, acc[0]); acc[1] = fmaf(w1, a1.y, acc[1]);
        }
    }
    for (; e < end; e++) {
        int s = g_src[e];
        float w = g_w[e];
        const float* zp = Z + (size_t)s * N + lane * CP;
        if (CP == 4) {
            float4 zv = *(const float4*)zp;
            acc[0] = fmaf(w, zv.x, acc[0]); acc[1] = fmaf(w, zv.y, acc[1]);
            acc[2] = fmaf(w, zv.z, acc[2]); acc[3] = fmaf(w, zv.w, acc[3]);
        } else {
            float2 zv = *(const float2*)zp;
            acc[0] = fmaf(w, zv.x, acc[0]); acc[1] = fmaf(w, zv.y, acc[1]);
        }
    }
#pragma unroll
    for (int j = 0; j < CP; j++) {
        float v = acc[j] + __ldg(&b[lane * CP + j]);
        H[(size_t)node * N + lane * CP + j] = v > 0.f ? v : 0.f;
    }
}

// ---------------- prototype distances + MLP readout + sigmoid + y ---------
__global__ void final_k(const float* __restrict__ H, const float* __restrict__ prot,
                        const float* __restrict__ Wf0, const float* __restrict__ bf0,
                        const float* __restrict__ Wf1, const float* __restrict__ bf1,
                        const void* __restrict__ y,
                        float* __restrict__ out, int n, int out_size) {
    __shared__ float sP[16 * 64];
    __shared__ float sPsq[16];
    __shared__ float sW0[16 * 8];
    __shared__ float sb0[8];
    __shared__ float sW1[8];
    __shared__ float sb1;
    for (int i = threadIdx.x; i < 16 * 64; i += blockDim.x) sP[i] = prot[i];
    if (threadIdx.x < 128) {
        if (threadIdx.x < 16 * 8) sW0[threadIdx.x] = Wf0[threadIdx.x];
        if (threadIdx.x < 8) { sb0[threadIdx.x] = bf0[threadIdx.x]; sW1[threadIdx.x] = Wf1[threadIdx.x]; }
        if (threadIdx.x == 0) sb1 = bf1[0];
    }
    __syncthreads();
    if (threadIdx.x < 16) {
        float s = 0.f;
        for (int k = 0; k < 64; k++) { float p = sP[threadIdx.x * 64 + k]; s += p * p; }
        sPsq[threadIdx.x] = s;
    }
    __syncthreads();

    int i = blockIdx.x * blockDim.x + threadIdx.x;
    if (i >= n) return;

    float dot[16];
#pragma unroll
    for (int j = 0; j < 16; j++) dot[j] = 0.f;
    float hh = 0.f;
    const float* h = H + (size_t)i * 64;
    for (int k = 0; k < 64; k++) {
        float hv = h[k];
        hh = fmaf(hv, hv, hh);
#pragma unroll
        for (int j = 0; j < 16; j++) dot[j] = fmaf(hv, sP[j * 64 + k], dot[j]);
    }
    float sim[16];
#pragma unroll
    for (int j = 0; j < 16; j++) {
        float d2 = hh + sPsq[j] - 2.f * dot[j];
        d2 = d2 > 0.f ? d2 : 0.f;
        sim[j] = logf((d2 + 1.0f) / (d2 + 1e-4f));
    }
    float o = sb1;
#pragma unroll
    for (int m = 0; m < 8; m++) {
        float t = sb0[m];
#pragma unroll
        for (int j = 0; j < 16; j++) t = fmaf(sim[j], sW0[j * 8 + m], t);
        float z = 0.5f * t * (1.0f + erff(t * 0.70710678118654752f));  // exact GELU
        o = fmaf(z, sW1[m], o);
    }
    out[i] = 1.0f / (1.0f + expf(-o));

    if (out_size >= 2 * n) {
        float yv;
        if (g_is64) yv = (float)((const long long*)y)[i];
        else        yv = (float)((const int*)y)[i];
        out[n + i] = yv;
    }
}

// ---------------- launch ----------------
extern "C" void kernel_launch(void* const* d_in, const int* in_sizes, int n_in,
                              void* d_out, int out_size) {
    const float* x    = (const float*)d_in[0];
    const void*  ei   = d_in[1];
    const void*  y    = d_in[2];
    const float* W1   = (const float*)d_in[3];
    const float* b1   = (const float*)d_in[4];
    const float* W2   = (const float*)d_in[5];
    const float* b2   = (const float*)d_in[6];
    const float* W3   = (const float*)d_in[7];
    const float* b3   = (const float*)d_in[8];
    const float* prot = (const float*)d_in[9];
    const float* Wf0  = (const float*)d_in[10];
    const float* bf0  = (const float*)d_in[11];
    const float* Wf1  = (const float*)d_in[12];
    const float* bf1  = (const float*)d_in[13];
    float* out = (float*)d_out;

    int n = in_sizes[0] / 128;
    int E = in_sizes[1] / 2;
    int nb = (n + SCAN_B - 1) / SCAN_B;

    void *pZ, *pH;
    cudaGetSymbolAddress(&pZ, g_Z);
    cudaGetSymbolAddress(&pH, g_H);
    float* Z = (float*)pZ;
    float* H = (float*)pH;

    detect_k<<<1, 256>>>((const int*)ei);
    init_k<<<(n + 255) / 256, 256>>>(n);
    count_k<<<(E + 255) / 256, 256>>>(ei, E);
    scan1_k<<<nb, SCAN_B>>>(n);
    scan2_k<<<1, 64>>>(nb);
    scan3_k<<<(n + 255) / 256, 256>>>(n, nb);
    fill_k<<<(E + 255) / 256, 256>>>(ei, E);

    int gemm_grid = (n + 31) / 32;           // 8 warps * 4 rows per block
    int agg_grid  = (n + 7) / 8;             // 8 warps (nodes) per block

    gemm_k<128, 128><<<gemm_grid, 256>>>(x, W1, Z, n);
    agg_k<128><<<agg_grid, 256>>>(Z, H, b1, n);
    gemm_k<128, 64><<<gemm_grid, 256>>>(H, W2, Z, n);
    agg_k<64><<<agg_grid, 256>>>(Z, H, b2, n);
    gemm_k<64, 64><<<gemm_grid, 256>>>(H, W3, Z, n);
    agg_k<64><<<agg_grid, 256>>>(Z, H, b3, n);

    final_k<<<(n + 127) / 128, 128>>>(H, prot, Wf0, bf0, Wf1, bf1, y, out, n, out_size);
}